// round 1
// baseline (speedup 1.0000x reference)
#include <cuda_runtime.h>

#define SIG_LEN  16777216
#define HOP      256
#define WIN      1024
#define PAD      768                       /* 3*HOP */
#define TOTAL    (SIG_LEN + 2*PAD)         /* 16778752 */
#define N_FRAMES 65539                     /* (TOTAL - WIN)/HOP + 1 */
#define N_ROWS   65542                     /* TOTAL / HOP */
#define HALF     513                       /* N_FFT/2 + 1 */

// One block = one frame. 512-point complex FFT of even/odd-packed real input,
// then untangle to the 513 rfft bins. Circular shift by 512 == multiply by (-1)^k.
__global__ __launch_bounds__(256) void stft_kernel(const float* __restrict__ x,
                                                   float* __restrict__ out) {
    __shared__ float sr[512];
    __shared__ float si[512];
    __shared__ float twr[513];   // tw[k] = exp(-i*pi*k/512)
    __shared__ float twi[513];

    const int t = threadIdx.x;
    const int f = blockIdx.x;
    const int start = f * HOP - PAD;   // signed offset into x for frame sample 0

    // Twiddle table (serves both stage twiddles and untangle twiddles).
    for (int k = t; k < 513; k += 256) {
        float s, c;
        sincospif(-(float)k * (1.0f / 512.0f), &s, &c);
        twr[k] = c;
        twi[k] = s;
    }

    // Load + Hamming window (w[j] = (0.54 - 0.46*cos(2*pi*j/1023)) / 32),
    // pack even/odd samples into complex, store bit-reversed (9-bit).
    #pragma unroll
    for (int q = 0; q < 2; q++) {
        int n  = t + q * 256;          // 0..511  (complex sample index)
        int j0 = 2 * n;                // even time index in frame
        int i0 = start + j0;
        float a = (i0     >= 0 && i0     < SIG_LEN) ? x[i0]     : 0.0f;
        float b = (i0 + 1 >= 0 && i0 + 1 < SIG_LEN) ? x[i0 + 1] : 0.0f;
        float w0 = (0.54f - 0.46f * cospif((float)(2 * j0)     * (1.0f / 1023.0f))) * 0.03125f;
        float w1 = (0.54f - 0.46f * cospif((float)(2 * j0 + 2) * (1.0f / 1023.0f))) * 0.03125f;
        int r = __brev(n) >> 23;       // reverse low 9 bits
        sr[r] = a * w0;
        si[r] = b * w1;
    }
    __syncthreads();

    // 9 radix-2 DIT stages (256 butterflies per stage, one per thread).
    #pragma unroll
    for (int s = 0; s < 9; s++) {
        int d = 1 << s;
        int m = t & (d - 1);
        int j = ((t >> s) << (s + 1)) | m;
        int ti = m << (9 - s);         // tw index for exp(-i*pi*m/d)
        float c  = twr[ti], sn = twi[ti];
        float ur = sr[j],     ui = si[j];
        float vr = sr[j + d], vi = si[j + d];
        float tr = vr * c - vi * sn;
        float tq = vr * sn + vi * c;
        sr[j]     = ur + tr;  si[j]     = ui + tq;
        sr[j + d] = ur - tr;  si[j + d] = ui - tq;
        __syncthreads();
    }

    // Untangle Z (512-pt complex FFT of packed reals) into X[k], k = 0..512:
    //   A = (Z[k] + conj(Z[512-k]))/2,  B = (Z[k] - conj(Z[512-k]))/2
    //   X[k] = A - i * W * B,  W = exp(-i*pi*k/512)
    // Then apply the zero-phase circular shift: X[k] *= (-1)^k.
    float* out_mag = out + (size_t)f * HALF;
    float* out_ph  = out + (size_t)N_ROWS * HALF + (size_t)f * HALF;
    for (int k = t; k <= 512; k += 256) {
        float Zkr = sr[k & 511], Zki = si[k & 511];
        int   km  = (512 - k) & 511;
        float Zmr = sr[km], Zmi = si[km];
        float Ar = 0.5f * (Zkr + Zmr), Ai = 0.5f * (Zki - Zmi);
        float Br = 0.5f * (Zkr - Zmr), Bi = 0.5f * (Zki + Zmi);
        float c  = twr[k], sn = twi[k];
        float wbr = c * Br - sn * Bi;       // real(W*B)
        float wbi = c * Bi + sn * Br;       // imag(W*B)
        float Xr = Ar + wbi;                // A - i*(W*B)
        float Xi = Ai - wbr;
        if (k & 1) { Xr = -Xr; Xi = -Xi; }  // (-1)^k shift factor
        out_mag[k] = sqrtf(Xr * Xr + Xi * Xi);
        out_ph[k]  = atan2f(Xi, Xr);
    }
}

// Rows [N_FRAMES, N_ROWS) of both planes stay zero (buffer is poisoned to 0xAA).
__global__ void zero_tail(float* __restrict__ out) {
    int i = blockIdx.x * blockDim.x + threadIdx.x;
    const int n = (N_ROWS - N_FRAMES) * HALF;   // 3 * 513 = 1539
    if (i < n) {
        out[(size_t)N_FRAMES * HALF + i] = 0.0f;
        out[(size_t)N_ROWS * HALF + (size_t)N_FRAMES * HALF + i] = 0.0f;
    }
}

extern "C" void kernel_launch(void* const* d_in, const int* in_sizes, int n_in,
                              void* d_out, int out_size) {
    const float* x = (const float*)d_in[0];
    float* out = (float*)d_out;
    stft_kernel<<<N_FRAMES, 256>>>(x, out);
    zero_tail<<<2, 1024>>>(out);
}

// round 2
// speedup vs baseline: 2.5001x; 2.5001x over previous
#include <cuda_runtime.h>

#define SIG_LEN  16777216
#define HOP      256
#define WIN      1024
#define PAD      768
#define N_FRAMES 65539
#define N_ROWS   65542
#define HALF     513

// XOR swizzle for conflict-free shared access (bijective on [0,512], keeps 513 range).
#define IDX(j) ((j) ^ (((j) >> 2) & 31))

__device__ float g_win[1024];
__device__ float g_twr[513];
__device__ float g_twi[513];

__global__ void init_tables() {
    int i = blockIdx.x * blockDim.x + threadIdx.x;
    if (i < 1024)
        g_win[i] = (0.54f - 0.46f * cospif((float)(2 * i) * (1.0f / 1023.0f))) * 0.03125f;
    if (i < 513) {
        float s, c;
        sincospif(-(float)i * (1.0f / 512.0f), &s, &c);
        g_twr[i] = c;
        g_twi[i] = s;
    }
}

__global__ void zero_tail(float* __restrict__ out) {
    int i = blockIdx.x * blockDim.x + threadIdx.x;
    const int n = (N_ROWS - N_FRAMES) * HALF;
    if (i < n) {
        out[(size_t)N_FRAMES * HALF + i] = 0.0f;
        out[(size_t)N_ROWS * HALF + (size_t)N_FRAMES * HALF + i] = 0.0f;
    }
}

// 2 frames per 256-thread block; 128 threads per frame.
// 512-pt complex FFT of even/odd-packed reals: 1 plain radix-4 stage +
// 3 twiddled fused radix-4 stages + 1 radix-2 stage, then real-FFT untangle.
__global__ __launch_bounds__(256) void stft_kernel(const float* __restrict__ x,
                                                   float* __restrict__ out) {
    __shared__ float sr[1024];   // 2 frames x 512
    __shared__ float si[1024];
    __shared__ float twr[513];
    __shared__ float twi[513];

    const int t    = threadIdx.x;
    const int half = t >> 7;
    const int lt   = t & 127;
    const int fo   = half << 9;                 // frame offset in shared
    const int f    = blockIdx.x * 2 + half;
    const int start = f * HOP - PAD;

    // Twiddle table -> shared (swizzled).
    for (int k = t; k < 513; k += 256) {
        int p = IDX(k);
        twr[p] = g_twr[k];
        twi[p] = g_twi[k];
    }

    // Load + window + even/odd pack + bit-reversed scatter.
    const bool inb = (start >= 0) && (start + WIN <= SIG_LEN);
    #pragma unroll
    for (int q = 0; q < 4; q++) {
        int n = lt + 128 * q;            // complex sample index 0..511
        float a, b;
        if (inb) {
            float2 v = ((const float2*)(x + start))[n];
            a = v.x; b = v.y;
        } else {
            int i0 = start + 2 * n;
            a = (i0     >= 0 && i0     < SIG_LEN) ? x[i0]     : 0.0f;
            b = (i0 + 1 >= 0 && i0 + 1 < SIG_LEN) ? x[i0 + 1] : 0.0f;
        }
        int r = __brev(n) >> 23;
        int p = fo + IDX(r);
        sr[p] = a * g_win[2 * n];
        si[p] = b * g_win[2 * n + 1];
    }
    __syncthreads();

    // Stage pair s=0,1 (all twiddles trivial: 1 and -i).
    {
        int base = 4 * lt;
        int p0 = fo + IDX(base),     p1 = fo + IDX(base + 1);
        int p2 = fo + IDX(base + 2), p3 = fo + IDX(base + 3);
        float a0r = sr[p0], a0i = si[p0], a1r = sr[p1], a1i = si[p1];
        float a2r = sr[p2], a2i = si[p2], a3r = sr[p3], a3i = si[p3];
        float b0r = a0r + a1r, b0i = a0i + a1i;
        float b1r = a0r - a1r, b1i = a0i - a1i;
        float b2r = a2r + a3r, b2i = a2i + a3i;
        float b3r = a2r - a3r, b3i = a2i - a3i;
        // stage 1: pair (b0,b2) w=1; pair (b1,b3) w=-i: -i*b3 = (b3i, -b3r)
        sr[p0] = b0r + b2r;  si[p0] = b0i + b2i;
        sr[p2] = b0r - b2r;  si[p2] = b0i - b2i;
        sr[p1] = b1r + b3i;  si[p1] = b1i - b3r;
        sr[p3] = b1r - b3i;  si[p3] = b1i + b3r;
    }
    __syncthreads();

    // Fused stage pairs s=(2,3),(4,5),(6,7).
    #pragma unroll
    for (int it = 1; it <= 3; it++) {
        const int S = 2 * it;
        const int d = 1 << S;
        int m    = lt & (d - 1);
        int base = ((lt >> S) << (S + 2)) | m;
        int p0 = fo + IDX(base),         p1 = fo + IDX(base + d);
        int p2 = fo + IDX(base + 2 * d), p3 = fo + IDX(base + 3 * d);
        float a0r = sr[p0], a0i = si[p0], a1r = sr[p1], a1i = si[p1];
        float a2r = sr[p2], a2i = si[p2], a3r = sr[p3], a3i = si[p3];
        int ts = IDX(m << (9 - S));
        float wsr = twr[ts], wsi = twi[ts];
        int ta = IDX(m << (8 - S));
        float war = twr[ta], wai = twi[ta];
        // stage S
        float t1r = a1r * wsr - a1i * wsi, t1i = a1r * wsi + a1i * wsr;
        float b0r = a0r + t1r, b0i = a0i + t1i;
        float b1r = a0r - t1r, b1i = a0i - t1i;
        float t3r = a3r * wsr - a3i * wsi, t3i = a3r * wsi + a3i * wsr;
        float b2r = a2r + t3r, b2i = a2i + t3i;
        float b3r = a2r - t3r, b3i = a2i - t3i;
        // stage S+1: w for (b0,b2) = wa; for (b1,b3) = -i*wa
        float u2r = b2r * war - b2i * wai, u2i = b2r * wai + b2i * war;
        float u3r = b3r * war - b3i * wai, u3i = b3r * wai + b3i * war;
        float v3r = u3i, v3i = -u3r;
        sr[p0] = b0r + u2r;  si[p0] = b0i + u2i;
        sr[p2] = b0r - u2r;  si[p2] = b0i - u2i;
        sr[p1] = b1r + v3r;  si[p1] = b1i + v3i;
        sr[p3] = b1r - v3r;  si[p3] = b1i - v3i;
        __syncthreads();
    }

    // Final radix-2 stage s=8 (stride 256); each thread does 2 butterflies.
    #pragma unroll
    for (int h = 0; h < 2; h++) {
        int j  = lt + 128 * h;
        int pj = fo + IDX(j), pk = fo + IDX(j + 256);
        int ti = IDX(j << 1);
        float wr = twr[ti], wi = twi[ti];
        float ur = sr[pj], ui = si[pj];
        float vr = sr[pk], vi = si[pk];
        float tr = vr * wr - vi * wi;
        float tq = vr * wi + vi * wr;
        sr[pj] = ur + tr;  si[pj] = ui + tq;
        sr[pk] = ur - tr;  si[pk] = ui - tq;
    }
    __syncthreads();

    // Untangle real FFT + (-1)^k circular-shift factor + mag/phase output.
    if (f < N_FRAMES) {
        float* om = out + (size_t)f * HALF;
        float* op = out + (size_t)N_ROWS * HALF + (size_t)f * HALF;
        #pragma unroll
        for (int q = 0; q < 5; q++) {
            int k = lt + 128 * q;
            if (q == 4) { if (lt != 0) break; k = 512; }
            int pk = fo + IDX(k & 511);
            float Zkr = sr[pk], Zki = si[pk];
            int km = (512 - k) & 511;
            int pm = fo + IDX(km);
            float Zmr = sr[pm], Zmi = si[pm];
            float Ar = 0.5f * (Zkr + Zmr), Ai = 0.5f * (Zki - Zmi);
            float Br = 0.5f * (Zkr - Zmr), Bi = 0.5f * (Zki + Zmi);
            int pt = IDX(k);
            float c = twr[pt], sn = twi[pt];
            float wbr = c * Br - sn * Bi;
            float wbi = c * Bi + sn * Br;
            float Xr = Ar + wbi;
            float Xi = Ai - wbr;
            if (k & 1) { Xr = -Xr; Xi = -Xi; }
            om[k] = sqrtf(Xr * Xr + Xi * Xi);
            op[k] = atan2f(Xi, Xr);
        }
    }
}

extern "C" void kernel_launch(void* const* d_in, const int* in_sizes, int n_in,
                              void* d_out, int out_size) {
    const float* x = (const float*)d_in[0];
    float* out = (float*)d_out;
    init_tables<<<4, 256>>>();
    zero_tail<<<2, 1024>>>(out);
    stft_kernel<<<(N_FRAMES + 1) / 2, 256>>>(x, out);
}